// round 3
// baseline (speedup 1.0000x reference)
#include <cuda_runtime.h>
#include <math.h>

#define NCH   256
#define FH    38
#define FW    38
#define PH    7
#define PW    7
#define SCALE 0.0625f

__global__ __launch_bounds__(256) void roipool_kernel(
    const float* __restrict__ feat,
    const float* __restrict__ rois,
    const int*   __restrict__ roib,
    float*       __restrict__ out)
{
    const int n = blockIdx.x;
    __shared__ int hs[PH], he[PH], ws[PW], we[PW];
    __shared__ int bofs;

    const int t = threadIdx.x;
    if (t < PH) {
        // Exact IEEE fp32 ops, EXCEPT division: emulate XLA-CPU fast-math,
        // which rewrites x/7 -> x * rn(1/7). rn(1/7) sits 4.4e-8 above 1/7,
        // which flips ceil(7*bin) at the last bin boundary for ~half the rois.
        const float R7 = 1.0f / 7.0f;   // compile-time correctly-rounded fp32 constant
        float x1 = floorf(__fadd_rn(__fmul_rn(rois[n * 4 + 0], SCALE), 0.5f));
        float y1 = floorf(__fadd_rn(__fmul_rn(rois[n * 4 + 1], SCALE), 0.5f));
        float x2 = floorf(__fadd_rn(__fmul_rn(rois[n * 4 + 2], SCALE), 0.5f));
        float y2 = floorf(__fadd_rn(__fmul_rn(rois[n * 4 + 3], SCALE), 0.5f));
        float roi_w = fmaxf(__fadd_rn(__fsub_rn(x2, x1), 1.0f), 1.0f);
        float roi_h = fmaxf(__fadd_rn(__fsub_rn(y2, y1), 1.0f), 1.0f);
        float bin_h = __fmul_rn(roi_h, R7);   // reciprocal-multiply, NOT exact divide
        float bin_w = __fmul_rn(roi_w, R7);
        float p = (float)t;
        float hsf = __fadd_rn(floorf(__fmul_rn(p, bin_h)), y1);
        float hef = __fadd_rn(ceilf(__fmul_rn(__fadd_rn(p, 1.0f), bin_h)), y1);
        float wsf = __fadd_rn(floorf(__fmul_rn(p, bin_w)), x1);
        float wef = __fadd_rn(ceilf(__fmul_rn(__fadd_rn(p, 1.0f), bin_w)), x1);
        hs[t] = (int)fminf(fmaxf(hsf, 0.0f), (float)FH);
        he[t] = (int)fminf(fmaxf(hef, 0.0f), (float)FH);
        ws[t] = (int)fminf(fmaxf(wsf, 0.0f), (float)FW);
        we[t] = (int)fminf(fmaxf(wef, 0.0f), (float)FW);
        if (t == 0) bofs = roib[n] * (NCH * FH * FW);
    }
    __syncthreads();

    const int base = bofs;
    const int total = NCH * PH * PW;   // 12544 outputs per ROI

    for (int idx = t; idx < total; idx += 256) {
        int c   = idx / (PH * PW);
        int bin = idx % (PH * PW);
        int ph  = bin / PW;
        int pw  = bin % PW;
        int h0 = hs[ph], h1 = he[ph];
        int w0 = ws[pw], w1 = we[pw];

        float m;
        if (h0 >= h1 || w0 >= w1) {
            m = 0.0f;   // empty bin -> 0 (reference maps -inf to 0)
        } else {
            m = -INFINITY;
            const float* f = feat + base + c * (FH * FW);
            for (int h = h0; h < h1; ++h) {
                const float* row = f + h * FW;
                for (int w = w0; w < w1; ++w) {
                    m = fmaxf(m, row[w]);
                }
            }
        }
        out[n * total + idx] = m;
    }
}

extern "C" void kernel_launch(void* const* d_in, const int* in_sizes, int n_in,
                              void* d_out, int out_size)
{
    const float* feat = (const float*)d_in[0];
    const float* rois = (const float*)d_in[1];
    const int*   rb   = (const int*)d_in[2];
    float*       out  = (float*)d_out;

    roipool_kernel<<<256, 256>>>(feat, rois, rb, out);
}

// round 4
// speedup vs baseline: 4.0435x; 4.0435x over previous
#include <cuda_runtime.h>
#include <math.h>

#define NCH   256
#define FH    38
#define FW    38
#define PH    7
#define PW    7
#define SCALE 0.0625f
#define BINS  (PH * PW)            // 49
#define TOTAL (NCH * BINS)         // 12544 outputs per ROI
#define SLICES (TOTAL / 256)       // 49 blocks of 256 threads per ROI

__global__ __launch_bounds__(256) void roipool_kernel(
    const float* __restrict__ feat,
    const float* __restrict__ rois,
    const int*   __restrict__ roib,
    float*       __restrict__ out)
{
    const int n = blockIdx.y;
    const int t = threadIdx.x;

    __shared__ int hs[PH], he[PH], ws[PW], we[PW];
    __shared__ int bofs;

    if (t < PH) {
        // Boundary math matches XLA-CPU fast-math reference bit-for-bit:
        // exact IEEE ops EXCEPT division lowered as x * rn(1/7).
        const float R7 = 1.0f / 7.0f;
        float x1 = floorf(__fadd_rn(__fmul_rn(rois[n * 4 + 0], SCALE), 0.5f));
        float y1 = floorf(__fadd_rn(__fmul_rn(rois[n * 4 + 1], SCALE), 0.5f));
        float x2 = floorf(__fadd_rn(__fmul_rn(rois[n * 4 + 2], SCALE), 0.5f));
        float y2 = floorf(__fadd_rn(__fmul_rn(rois[n * 4 + 3], SCALE), 0.5f));
        float roi_w = fmaxf(__fadd_rn(__fsub_rn(x2, x1), 1.0f), 1.0f);
        float roi_h = fmaxf(__fadd_rn(__fsub_rn(y2, y1), 1.0f), 1.0f);
        float bin_h = __fmul_rn(roi_h, R7);
        float bin_w = __fmul_rn(roi_w, R7);
        float p = (float)t;
        float hsf = __fadd_rn(floorf(__fmul_rn(p, bin_h)), y1);
        float hef = __fadd_rn(ceilf(__fmul_rn(__fadd_rn(p, 1.0f), bin_h)), y1);
        float wsf = __fadd_rn(floorf(__fmul_rn(p, bin_w)), x1);
        float wef = __fadd_rn(ceilf(__fmul_rn(__fadd_rn(p, 1.0f), bin_w)), x1);
        hs[t] = (int)fminf(fmaxf(hsf, 0.0f), (float)FH);
        he[t] = (int)fminf(fmaxf(hef, 0.0f), (float)FH);
        ws[t] = (int)fminf(fmaxf(wsf, 0.0f), (float)FW);
        we[t] = (int)fminf(fmaxf(wef, 0.0f), (float)FW);
        if (t == 0) bofs = roib[n] * (NCH * FH * FW);
    }
    __syncthreads();

    // One output element per thread.
    const int idx = blockIdx.x * 256 + t;          // 0..12543
    const int c   = idx / BINS;
    const int bin = idx - c * BINS;
    const int ph  = bin / PW;
    const int pw  = bin - ph * PW;

    const int h0 = hs[ph], h1 = he[ph];
    const int w0 = ws[pw], w1 = we[pw];

    const float* __restrict__ f = feat + bofs + c * (FH * FW);

    // Bin spans are provably <= 4x4 for this problem (roi dims <= 20).
    // Fully unrolled: 16 independent, always-in-bounds loads (MLP=16),
    // validity handled by predicated fmax. No divergence, no loop overhead.
    float m = -INFINITY;
#pragma unroll
    for (int dh = 0; dh < 4; ++dh) {
        const int  h  = h0 + dh;
        const bool hv = h < h1;
        const int  hc = min(h, FH - 1);
        const float* row = f + hc * FW;
#pragma unroll
        for (int dw = 0; dw < 4; ++dw) {
            const int  w  = w0 + dw;
            const float v = row[min(w, FW - 1)];
            if (hv && (w < w1)) m = fmaxf(m, v);
        }
    }
    if (m == -INFINITY) m = 0.0f;   // empty bin -> 0 per reference

    out[n * TOTAL + idx] = m;
}

extern "C" void kernel_launch(void* const* d_in, const int* in_sizes, int n_in,
                              void* d_out, int out_size)
{
    const float* feat = (const float*)d_in[0];
    const float* rois = (const float*)d_in[1];
    const int*   rb   = (const int*)d_in[2];
    float*       out  = (float*)d_out;

    dim3 grid(SLICES, 256);
    roipool_kernel<<<grid, 256>>>(feat, rois, rb, out);
}

// round 5
// speedup vs baseline: 5.5298x; 1.3676x over previous
#include <cuda_runtime.h>
#include <math.h>

#define NCH   256
#define FH    38
#define FW    38
#define PH    7
#define PW    7
#define SCALE 0.0625f
#define BINS  (PH * PW)            // 49
#define TOTAL (NCH * BINS)         // 12544 outputs per ROI
#define SLICES (TOTAL / 256)       // 49 blocks of 256 threads per ROI

__global__ __launch_bounds__(256) void roipool_kernel(
    const float* __restrict__ feat,
    const float* __restrict__ rois,
    const int*   __restrict__ roib,
    float*       __restrict__ out)
{
    const int n = blockIdx.y;
    const int t = threadIdx.x;

    __shared__ int      sbinoff[BINS];   // h0*FW + w0 per bin
    __shared__ unsigned smask[BINS];     // 4x4 validity bitmask per bin
    __shared__ int      bofs;

    if (t < BINS) {
        // Boundary math matches XLA-CPU fast-math reference bit-for-bit:
        // exact IEEE ops EXCEPT division lowered as x * rn(1/7).
        const float R7 = 1.0f / 7.0f;
        float x1 = floorf(__fadd_rn(__fmul_rn(rois[n * 4 + 0], SCALE), 0.5f));
        float y1 = floorf(__fadd_rn(__fmul_rn(rois[n * 4 + 1], SCALE), 0.5f));
        float x2 = floorf(__fadd_rn(__fmul_rn(rois[n * 4 + 2], SCALE), 0.5f));
        float y2 = floorf(__fadd_rn(__fmul_rn(rois[n * 4 + 3], SCALE), 0.5f));
        float roi_w = fmaxf(__fadd_rn(__fsub_rn(x2, x1), 1.0f), 1.0f);
        float roi_h = fmaxf(__fadd_rn(__fsub_rn(y2, y1), 1.0f), 1.0f);
        float bin_h = __fmul_rn(roi_h, R7);
        float bin_w = __fmul_rn(roi_w, R7);

        int ph = t / PW;
        int pw = t - ph * PW;
        float fph = (float)ph, fpw = (float)pw;

        int h0 = (int)fminf(fmaxf(__fadd_rn(floorf(__fmul_rn(fph, bin_h)), y1), 0.0f), (float)FH);
        int h1 = (int)fminf(fmaxf(__fadd_rn(ceilf(__fmul_rn(__fadd_rn(fph, 1.0f), bin_h)), y1), 0.0f), (float)FH);
        int w0 = (int)fminf(fmaxf(__fadd_rn(floorf(__fmul_rn(fpw, bin_w)), x1), 0.0f), (float)FW);
        int w1 = (int)fminf(fmaxf(__fadd_rn(ceilf(__fmul_rn(__fadd_rn(fpw, 1.0f), bin_w)), x1), 0.0f), (float)FW);

        // 16-bit validity mask (spans are provably <= 4 for this problem).
        // Valid => h < h1 <= 38, w < w1 <= 38 => always in-bounds, no clamps.
        unsigned mh = 0, mw = 0;
#pragma unroll
        for (int d = 0; d < 4; ++d) {
            mh |= (h0 + d < h1) ? (1u << d) : 0u;
            mw |= (w0 + d < w1) ? (1u << d) : 0u;
        }
        unsigned mask = 0;
#pragma unroll
        for (int d = 0; d < 4; ++d)
            mask |= ((mh >> d) & 1u) ? (mw << (4 * d)) : 0u;

        sbinoff[t] = h0 * FW + w0;
        smask[t]   = mask;
        if (t == 0) bofs = roib[n] * (NCH * FH * FW);
    }
    __syncthreads();

    // One output element per thread.
    const int idx = blockIdx.x * 256 + t;          // 0..12543
    const int c   = idx / BINS;                    // magic-number division
    const int bin = idx - c * BINS;

    const unsigned mask = smask[bin];
    const float* __restrict__ f = feat + bofs + c * (FH * FW) + sbinoff[bin];

    // 16 candidates at compile-time-constant offsets; predicated load+max.
    float m = -INFINITY;
#pragma unroll
    for (int dh = 0; dh < 4; ++dh) {
#pragma unroll
        for (int dw = 0; dw < 4; ++dw) {
            if (mask & (1u << (dh * 4 + dw)))
                m = fmaxf(m, f[dh * FW + dw]);
        }
    }
    if (m == -INFINITY) m = 0.0f;   // empty bin -> 0 per reference

    out[n * TOTAL + idx] = m;
}

extern "C" void kernel_launch(void* const* d_in, const int* in_sizes, int n_in,
                              void* d_out, int out_size)
{
    const float* feat = (const float*)d_in[0];
    const float* rois = (const float*)d_in[1];
    const int*   rb   = (const int*)d_in[2];
    float*       out  = (float*)d_out;

    dim3 grid(SLICES, 256);
    roipool_kernel<<<grid, 256>>>(feat, rois, rb, out);
}